// round 3
// baseline (speedup 1.0000x reference)
#include <cuda_runtime.h>
#include <cstdint>
#include <math.h>

#define NP 8192   // particles == channels

// ---------------- device scratch (no allocations allowed) ----------------
__device__ float g_state[NP * 3];
__device__ float g_invw[NP];
__device__ float g_sum[3];
__device__ int   g_done;

// ---------------- threefry2x32 (JAX rotation schedule) -------------------
// Partitionable mode: 32-bit draw at flat index n is y0^y1 of the block with
// counter (x0=hi=0, x1=lo=n).
__device__ __forceinline__ uint32_t tf32(uint32_t k0, uint32_t k1, uint32_t n)
{
    uint32_t k2 = k0 ^ k1 ^ 0x1BD11BDAu;
    uint32_t x0 = k0;          // 0 + ks[0]
    uint32_t x1 = n + k1;      // n + ks[1]
#define TFR(r) { x0 += x1; x1 = __funnelshift_l(x1, x1, (r)); x1 ^= x0; }
    TFR(13) TFR(15) TFR(26) TFR(6)
    x0 += k1; x1 += k2 + 1u;
    TFR(17) TFR(29) TFR(16) TFR(24)
    x0 += k2; x1 += k0 + 2u;
    TFR(13) TFR(15) TFR(26) TFR(6)
    x0 += k0; x1 += k1 + 3u;
    TFR(17) TFR(29) TFR(16) TFR(24)
    x0 += k1; x1 += k2 + 4u;
    TFR(13) TFR(15) TFR(26) TFR(6)
    x0 += k2; x1 += k0 + 5u;
#undef TFR
    return x0 ^ x1;
}

// ---------------- kernel A: state transition + process noise -------------
__global__ void k_state(const float* __restrict__ sv,
                        const float* __restrict__ T,
                        const float* __restrict__ Q,
                        uint32_t kn0, uint32_t kn1)
{
    int p = blockIdx.x * blockDim.x + threadIdx.x;
    if (p < 3) g_sum[p] = 0.0f;   // reset accumulators each launch (graph replay)
    if (p == 3) g_done = 0;
    if (p >= NP) return;

    // 3x3 Cholesky (redundant per-thread; trivial cost)
    float l00 = sqrtf(Q[0]);
    float l10 = Q[3] / l00, l20 = Q[6] / l00;
    float l11 = sqrtf(Q[4] - l10 * l10);
    float l21 = (Q[7] - l20 * l10) / l11;
    float l22 = sqrtf(Q[8] - l20 * l20 - l21 * l21);

    // z ~ N(0,1) via sqrt(2)*erfinv(uniform(-1+eps, 1)), matching jax.random.normal
    float z[3];
#pragma unroll
    for (int d = 0; d < 3; ++d) {
        uint32_t b = tf32(kn0, kn1, (uint32_t)(3 * p + d));
        float f = __uint_as_float(0x3f800000u | (b >> 9)) - 1.0f;
        float val = __fadd_rn(__fmul_rn(f, 2.0f), -0.99999994f); // f*(hi-lo)+lo, no fma
        val = fmaxf(-0.99999994f, val);
        z[d] = 1.41421356237f * erfinvf(val);
    }

    float s0 = sv[3 * p], s1 = sv[3 * p + 1], s2 = sv[3 * p + 2];
    float u0 = T[0] * s0 + T[1] * s1 + T[2] * s2;
    float u1 = T[3] * s0 + T[4] * s1 + T[5] * s2;
    float u2 = T[6] * s0 + T[7] * s1 + T[8] * s2;

    // state = updated + z @ L  (L lower triangular)
    g_state[3 * p + 0] = u0 + z[0] * l00 + z[1] * l10 + z[2] * l20;
    g_state[3 * p + 1] = u1 + z[1] * l11 + z[2] * l21;
    g_state[3 * p + 2] = u2 + z[2] * l22;
}

// ---------------- kernel B: w[a] = sum_b (x[a,b] - F[b].s_a)^2 ------------
#define CHB   2048              // b-chunk size (floats per plane)
#define CHB4  (CHB / 4)         // 512 float4 per plane
#define FPITCH 2056             // plane pitch in floats

__global__ void k_weights(const float* __restrict__ x, const float* __restrict__ F)
{
    extern __shared__ float sF[]; // 3 * FPITCH floats = 24672 B

    int tid = threadIdx.x, warp = tid >> 5, lane = tid & 31;
    int a0 = blockIdx.x * 16 + warp * 2;
    int a1 = a0 + 1;

    float s00 = g_state[3 * a0], s01 = g_state[3 * a0 + 1], s02 = g_state[3 * a0 + 2];
    float s10 = g_state[3 * a1], s11 = g_state[3 * a1 + 1], s12 = g_state[3 * a1 + 2];

    const float4* x0 = reinterpret_cast<const float4*>(x + (size_t)a0 * NP);
    const float4* x1 = reinterpret_cast<const float4*>(x + (size_t)a1 * NP);
    const float4* f0 = reinterpret_cast<const float4*>(sF);
    const float4* f1 = reinterpret_cast<const float4*>(sF + FPITCH);
    const float4* f2 = reinterpret_cast<const float4*>(sF + 2 * FPITCH);

    float acc0 = 0.0f, acc1 = 0.0f;

    for (int c = 0; c < NP / CHB; ++c) {
        __syncthreads();
        for (int i = tid; i < CHB * 3; i += 256) {
            float v = __ldg(F + c * (CHB * 3) + i);
            sF[(i % 3) * FPITCH + (i / 3)] = v;
        }
        __syncthreads();

        int base4 = c * CHB4;
#pragma unroll 4
        for (int it = 0; it < CHB4 / 32; ++it) {
            int q = it * 32 + lane;
            float4 xa = __ldg(x0 + base4 + q);
            float4 xb = __ldg(x1 + base4 + q);
            float4 fa = f0[q], fb = f1[q], fc = f2[q];
            float p, d;
            p = fa.x * s00; p = fmaf(fb.x, s01, p); p = fmaf(fc.x, s02, p); d = xa.x - p; acc0 = fmaf(d, d, acc0);
            p = fa.y * s00; p = fmaf(fb.y, s01, p); p = fmaf(fc.y, s02, p); d = xa.y - p; acc0 = fmaf(d, d, acc0);
            p = fa.z * s00; p = fmaf(fb.z, s01, p); p = fmaf(fc.z, s02, p); d = xa.z - p; acc0 = fmaf(d, d, acc0);
            p = fa.w * s00; p = fmaf(fb.w, s01, p); p = fmaf(fc.w, s02, p); d = xa.w - p; acc0 = fmaf(d, d, acc0);
            p = fa.x * s10; p = fmaf(fb.x, s11, p); p = fmaf(fc.x, s12, p); d = xb.x - p; acc1 = fmaf(d, d, acc1);
            p = fa.y * s10; p = fmaf(fb.y, s11, p); p = fmaf(fc.y, s12, p); d = xb.y - p; acc1 = fmaf(d, d, acc1);
            p = fa.z * s10; p = fmaf(fb.z, s11, p); p = fmaf(fc.z, s12, p); d = xb.z - p; acc1 = fmaf(d, d, acc1);
            p = fa.w * s10; p = fmaf(fb.w, s11, p); p = fmaf(fc.w, s12, p); d = xb.w - p; acc1 = fmaf(d, d, acc1);
        }
    }

#pragma unroll
    for (int o = 16; o; o >>= 1) {
        acc0 += __shfl_down_sync(0xffffffffu, acc0, o);
        acc1 += __shfl_down_sync(0xffffffffu, acc1, o);
    }
    if (lane == 0) {
        g_invw[a0] = 1.0f / acc0;
        g_invw[a1] = 1.0f / acc1;
    }
}

// ---------------- kernel C: categorical + fused mean-of-gathered ----------
// argmax_j( -log(-log u_ij) + log w_j ) == argmin_j( (-log u_ij) * (1/w_j) )
// Pruning: with s = 1-u (exact, s = 2-t for t in [1,2)):
//   s <= -log(u)                 -> safe lower bound for skipping
//   -log(u) <= s + s^2  (u>=.34) -> safe upper bound feeding the threshold
// Winners/ties are ALWAYS evaluated through the exact logf path (identical
// arithmetic to the round-1 passing kernel), so index selection is unchanged.
__global__ void k_cat(uint32_t kc0, uint32_t kc1, float* __restrict__ out)
{
    const int row = blockIdx.x;
    const int t = threadIdx.x;
    const float INF = __int_as_float(0x7f800000);
    float mv = INF;           // exact running min (only exact v's enter)
    int   mi = 0;
    float thr = INF;          // provable upper bound on the final row min
    uint32_t nb = (uint32_t)row * (uint32_t)NP + (uint32_t)t;

    for (int k = 0; k < NP / 256; ++k) {
        int j = t + (k << 8);
        uint32_t b = tf32(kc0, kc1, nb + (uint32_t)(k << 8));
        float tt = __uint_as_float(0x3f800000u | (b >> 9));  // in [1,2)
        float invw = __ldg(&g_invw[j]);
        float s  = 2.0f - tt;                 // = 1-u exactly
        float ss = fmaf(s, s, s);             // s + s^2 (real upper bd for u>=.34)
        float ub = (ss * 1.00002f) * invw;    // fudged: ub >= true v (when valid)
        if (tt > 1.34f) thr = fminf(thr, ub); // validity of the series bound
        bool maybe = (s * 0.99998f) * invw <= thr;  // fudged lower bound test
        unsigned m = __ballot_sync(0xffffffffu, maybe);
        if (m) {
            // exact path — identical arithmetic to the reference mapping
            float u = tt - 1.0f;
            u = fmaxf(u, 1.17549435e-38f);
            float e = -logf(u);
            float v = e * invw;
            if (v < mv) { mv = v; mi = j; }   // strict <: first index wins
            thr = fminf(thr, v);              // tighten threshold with exact v
        }
        if (k & 1) {
            // share the threshold across the warp (min-butterfly)
#pragma unroll
            for (int o = 16; o; o >>= 1)
                thr = fminf(thr, __shfl_xor_sync(0xffffffffu, thr, o));
        }
    }

    // block argmin reduce (value, then lower index on exact ties)
    int lane = t & 31, warp = t >> 5;
#pragma unroll
    for (int o = 16; o; o >>= 1) {
        float ov = __shfl_down_sync(0xffffffffu, mv, o);
        int   oi = __shfl_down_sync(0xffffffffu, mi, o);
        if (ov < mv || (ov == mv && oi < mi)) { mv = ov; mi = oi; }
    }
    __shared__ float shv[8];
    __shared__ int   shi[8];
    if (lane == 0) { shv[warp] = mv; shi[warp] = mi; }
    __syncthreads();
    if (warp == 0) {
        float v2 = (lane < 8) ? shv[lane] : INF;
        int   i2 = (lane < 8) ? shi[lane] : 0x7fffffff;
#pragma unroll
        for (int o = 4; o; o >>= 1) {
            float ov = __shfl_down_sync(0xffffffffu, v2, o);
            int   oi = __shfl_down_sync(0xffffffffu, i2, o);
            if (ov < v2 || (ov == v2 && oi < i2)) { v2 = ov; i2 = oi; }
        }
        if (lane == 0) {
            atomicAdd(&g_sum[0], g_state[3 * i2 + 0]);
            atomicAdd(&g_sum[1], g_state[3 * i2 + 1]);
            atomicAdd(&g_sum[2], g_state[3 * i2 + 2]);
            __threadfence();
            if (atomicAdd(&g_done, 1) == (int)gridDim.x - 1) {
                out[0] = g_sum[0] * (1.0f / NP);
                out[1] = g_sum[1] * (1.0f / NP);
                out[2] = g_sum[2] * (1.0f / NP);
            }
        }
    }
}

// ---------------- host: key derivation (fold-like split) ------------------
static void h_tf(uint32_t k0, uint32_t k1, uint32_t x0, uint32_t x1,
                 uint32_t& y0, uint32_t& y1)
{
    uint32_t k2 = k0 ^ k1 ^ 0x1BD11BDAu;
    x0 += k0; x1 += k1;
    const int R0[4] = {13, 15, 26, 6}, R1[4] = {17, 29, 16, 24};
    const int* RS[5] = {R0, R1, R0, R1, R0};
    const uint32_t ks[3] = {k0, k1, k2};
    for (int g = 0; g < 5; ++g) {
        for (int q = 0; q < 4; ++q) {
            x0 += x1;
            int r = RS[g][q];
            x1 = (x1 << r) | (x1 >> (32 - r));
            x1 ^= x0;
        }
        x0 += ks[(g + 1) % 3];
        x1 += ks[(g + 2) % 3] + (uint32_t)(g + 1);
    }
    y0 = x0; y1 = x1;
}

extern "C" void kernel_launch(void* const* d_in, const int* in_sizes, int n_in,
                              void* d_out, int out_size)
{
    const float* x  = (const float*)d_in[0];  // inputs (1, C, P)
    const float* sv = (const float*)d_in[1];  // state_vector (P, 3)
    const float* T  = (const float*)d_in[2];  // transition (3, 3)
    const float* Q  = (const float*)d_in[3];  // process noise cov (3, 3)
    const float* F  = (const float*)d_in[4];  // forward_matrix (C, 3)

    uint32_t kn0, kn1, kc0, kc1;
    h_tf(0u, 42u, 0u, 0u, kn0, kn1);  // k_noise
    h_tf(0u, 42u, 0u, 1u, kc0, kc1);  // k_cat

    const int smem = 3 * FPITCH * (int)sizeof(float);

    k_state  <<<NP / 256, 256>>>(sv, T, Q, kn0, kn1);
    k_weights<<<NP / 16,  256, smem>>>(x, F);
    k_cat    <<<NP,       256>>>(kc0, kc1, (float*)d_out);
}

// round 4
// speedup vs baseline: 1.1144x; 1.1144x over previous
#include <cuda_runtime.h>
#include <cstdint>
#include <math.h>

#define NP 8192   // particles == channels

// ---------------- device scratch (no allocations allowed) ----------------
__device__ float g_state[NP * 3];
__device__ float g_invw[NP];
__device__ float g_sum[3];
__device__ int   g_done;

// ---------------- threefry2x32 (JAX rotation schedule) -------------------
// Partitionable mode: 32-bit draw at flat index n is y0^y1 of the block with
// counter (x0=hi=0, x1=lo=n).
__device__ __forceinline__ uint32_t tf32(uint32_t k0, uint32_t k1, uint32_t n)
{
    uint32_t k2 = k0 ^ k1 ^ 0x1BD11BDAu;
    uint32_t x0 = k0;          // 0 + ks[0]
    uint32_t x1 = n + k1;      // n + ks[1]
#define TFR(r) { x0 += x1; x1 = __funnelshift_l(x1, x1, (r)); x1 ^= x0; }
    TFR(13) TFR(15) TFR(26) TFR(6)
    x0 += k1; x1 += k2 + 1u;
    TFR(17) TFR(29) TFR(16) TFR(24)
    x0 += k2; x1 += k0 + 2u;
    TFR(13) TFR(15) TFR(26) TFR(6)
    x0 += k0; x1 += k1 + 3u;
    TFR(17) TFR(29) TFR(16) TFR(24)
    x0 += k1; x1 += k2 + 4u;
    TFR(13) TFR(15) TFR(26) TFR(6)
    x0 += k2; x1 += k0 + 5u;
#undef TFR
    return x0 ^ x1;
}

// ---------------- kernel A: state transition + process noise -------------
__global__ void k_state(const float* __restrict__ sv,
                        const float* __restrict__ T,
                        const float* __restrict__ Q,
                        uint32_t kn0, uint32_t kn1)
{
    int p = blockIdx.x * blockDim.x + threadIdx.x;
    if (p < 3) g_sum[p] = 0.0f;   // reset accumulators each launch (graph replay)
    if (p == 3) g_done = 0;
    if (p >= NP) return;

    // 3x3 Cholesky (redundant per-thread; trivial cost)
    float l00 = sqrtf(Q[0]);
    float l10 = Q[3] / l00, l20 = Q[6] / l00;
    float l11 = sqrtf(Q[4] - l10 * l10);
    float l21 = (Q[7] - l20 * l10) / l11;
    float l22 = sqrtf(Q[8] - l20 * l20 - l21 * l21);

    // z ~ N(0,1) via sqrt(2)*erfinv(uniform(-1+eps, 1)), matching jax.random.normal
    float z[3];
#pragma unroll
    for (int d = 0; d < 3; ++d) {
        uint32_t b = tf32(kn0, kn1, (uint32_t)(3 * p + d));
        float f = __uint_as_float(0x3f800000u | (b >> 9)) - 1.0f;
        float val = __fadd_rn(__fmul_rn(f, 2.0f), -0.99999994f); // f*(hi-lo)+lo, no fma
        val = fmaxf(-0.99999994f, val);
        z[d] = 1.41421356237f * erfinvf(val);
    }

    float s0 = sv[3 * p], s1 = sv[3 * p + 1], s2 = sv[3 * p + 2];
    float u0 = T[0] * s0 + T[1] * s1 + T[2] * s2;
    float u1 = T[3] * s0 + T[4] * s1 + T[5] * s2;
    float u2 = T[6] * s0 + T[7] * s1 + T[8] * s2;

    // state = updated + z @ L  (L lower triangular)
    g_state[3 * p + 0] = u0 + z[0] * l00 + z[1] * l10 + z[2] * l20;
    g_state[3 * p + 1] = u1 + z[1] * l11 + z[2] * l21;
    g_state[3 * p + 2] = u2 + z[2] * l22;
}

// ---------------- kernel B: w[a] = sum_b (x[a,b] - F[b].s_a)^2 ------------
// Round-1 form (measured faster than smem staging): one warp per row a;
// float4 loads of the contiguous inputs row; F served from L1/L2.
__global__ void k_weights(const float* __restrict__ x, const float* __restrict__ F)
{
    int warp = threadIdx.x >> 5, lane = threadIdx.x & 31;
    int a = blockIdx.x * 8 + warp;

    float s0 = g_state[3 * a], s1 = g_state[3 * a + 1], s2 = g_state[3 * a + 2];
    const float4* xrow = reinterpret_cast<const float4*>(x + (size_t)a * NP);
    const float4* Fv   = reinterpret_cast<const float4*>(F); // F is (NP,3) contiguous

    float acc = 0.0f;
#pragma unroll 4
    for (int t = 0; t < NP / 128; ++t) {
        int b4 = t * 32 + lane;                 // float4 index within the row
        float4 xv = __ldg(xrow + b4);
        float4 f0 = __ldg(Fv + 3 * b4 + 0);     // 12 consecutive floats = F rows b..b+3
        float4 f1 = __ldg(Fv + 3 * b4 + 1);
        float4 f2 = __ldg(Fv + 3 * b4 + 2);
        float p0 = f0.x * s0 + f0.y * s1 + f0.z * s2;
        float p1 = f0.w * s0 + f1.x * s1 + f1.y * s2;
        float p2 = f1.z * s0 + f1.w * s1 + f2.x * s2;
        float p3 = f2.y * s0 + f2.z * s1 + f2.w * s2;
        float d0 = xv.x - p0, d1 = xv.y - p1, d2 = xv.z - p2, d3 = xv.w - p3;
        acc = fmaf(d0, d0, acc); acc = fmaf(d1, d1, acc);
        acc = fmaf(d2, d2, acc); acc = fmaf(d3, d3, acc);
    }
#pragma unroll
    for (int o = 16; o; o >>= 1) acc += __shfl_down_sync(0xffffffffu, acc, o);
    if (lane == 0) g_invw[a] = 1.0f / acc;
}

// ---------------- kernel C: categorical + fused mean-of-gathered ----------
// argmax_j( -log(-log u_ij) + log w_j ) == argmin_j( (-log u_ij) * (1/w_j) )
// Plain exact loop (round-1 arithmetic, bit-identical selection).
__global__ void k_cat(uint32_t kc0, uint32_t kc1, float* __restrict__ out)
{
    const int row = blockIdx.x;
    const int t = threadIdx.x;
    const float INF = __int_as_float(0x7f800000);
    float mv = INF;
    int   mi = 0;
    uint32_t nb = (uint32_t)row * (uint32_t)NP + (uint32_t)t;

#pragma unroll 4
    for (int k = 0; k < NP / 256; ++k) {
        int j = t + (k << 8);
        uint32_t b = tf32(kc0, kc1, nb + (uint32_t)(k << 8));
        // t = 1 + (b>>9)/2^23 built on the fma pipe: umulhi(b,2^23) == b>>9,
        // and since b>>9 < 2^23 the OR with 0x3f800000 equals an ADD.
        uint32_t tbits = __umulhi(b, 0x00800000u) + 0x3f800000u;
        float f = __uint_as_float(tbits) - 1.0f;       // uniform in [0,1), exact
        float u = fmaxf(f, 1.17549435e-38f);           // uniform(tiny, 1)
        float e = -logf(u);                            // Exp(1) variate
        float v = e * __ldg(&g_invw[j]);
        if (v < mv) { mv = v; mi = j; }                // strict <: first index wins
    }

    // block argmin reduce (value, then lower index on exact ties)
    int lane = t & 31, warp = t >> 5;
#pragma unroll
    for (int o = 16; o; o >>= 1) {
        float ov = __shfl_down_sync(0xffffffffu, mv, o);
        int   oi = __shfl_down_sync(0xffffffffu, mi, o);
        if (ov < mv || (ov == mv && oi < mi)) { mv = ov; mi = oi; }
    }
    __shared__ float shv[8];
    __shared__ int   shi[8];
    if (lane == 0) { shv[warp] = mv; shi[warp] = mi; }
    __syncthreads();
    if (warp == 0) {
        float v2 = (lane < 8) ? shv[lane] : INF;
        int   i2 = (lane < 8) ? shi[lane] : 0x7fffffff;
#pragma unroll
        for (int o = 4; o; o >>= 1) {
            float ov = __shfl_down_sync(0xffffffffu, v2, o);
            int   oi = __shfl_down_sync(0xffffffffu, i2, o);
            if (ov < v2 || (ov == v2 && oi < i2)) { v2 = ov; i2 = oi; }
        }
        if (lane == 0) {
            atomicAdd(&g_sum[0], g_state[3 * i2 + 0]);
            atomicAdd(&g_sum[1], g_state[3 * i2 + 1]);
            atomicAdd(&g_sum[2], g_state[3 * i2 + 2]);
            __threadfence();
            if (atomicAdd(&g_done, 1) == (int)gridDim.x - 1) {
                out[0] = g_sum[0] * (1.0f / NP);
                out[1] = g_sum[1] * (1.0f / NP);
                out[2] = g_sum[2] * (1.0f / NP);
            }
        }
    }
}

// ---------------- host: key derivation (fold-like split) ------------------
static void h_tf(uint32_t k0, uint32_t k1, uint32_t x0, uint32_t x1,
                 uint32_t& y0, uint32_t& y1)
{
    uint32_t k2 = k0 ^ k1 ^ 0x1BD11BDAu;
    x0 += k0; x1 += k1;
    const int R0[4] = {13, 15, 26, 6}, R1[4] = {17, 29, 16, 24};
    const int* RS[5] = {R0, R1, R0, R1, R0};
    const uint32_t ks[3] = {k0, k1, k2};
    for (int g = 0; g < 5; ++g) {
        for (int q = 0; q < 4; ++q) {
            x0 += x1;
            int r = RS[g][q];
            x1 = (x1 << r) | (x1 >> (32 - r));
            x1 ^= x0;
        }
        x0 += ks[(g + 1) % 3];
        x1 += ks[(g + 2) % 3] + (uint32_t)(g + 1);
    }
    y0 = x0; y1 = x1;
}

extern "C" void kernel_launch(void* const* d_in, const int* in_sizes, int n_in,
                              void* d_out, int out_size)
{
    const float* x  = (const float*)d_in[0];  // inputs (1, C, P)
    const float* sv = (const float*)d_in[1];  // state_vector (P, 3)
    const float* T  = (const float*)d_in[2];  // transition (3, 3)
    const float* Q  = (const float*)d_in[3];  // process noise cov (3, 3)
    const float* F  = (const float*)d_in[4];  // forward_matrix (C, 3)

    uint32_t kn0, kn1, kc0, kc1;
    h_tf(0u, 42u, 0u, 0u, kn0, kn1);  // k_noise
    h_tf(0u, 42u, 0u, 1u, kc0, kc1);  // k_cat

    k_state  <<<NP / 256, 256>>>(sv, T, Q, kn0, kn1);
    k_weights<<<NP / 8,   256>>>(x, F);
    k_cat    <<<NP,       256>>>(kc0, kc1, (float*)d_out);
}

// round 5
// speedup vs baseline: 1.2203x; 1.0951x over previous
#include <cuda_runtime.h>
#include <cstdint>
#include <math.h>

#define NP 8192   // particles == channels

// ---------------- device scratch (no allocations allowed) ----------------
__device__ float g_state[NP * 3];
__device__ float g_invw[NP];
__device__ float g_sum[3];
__device__ int   g_done;

// ---------------- threefry2x32 (JAX rotation schedule) -------------------
__device__ __forceinline__ uint32_t tf32(uint32_t k0, uint32_t k1, uint32_t n)
{
    uint32_t k2 = k0 ^ k1 ^ 0x1BD11BDAu;
    uint32_t x0 = k0;          // 0 + ks[0]
    uint32_t x1 = n + k1;      // n + ks[1]
#define TFR(r) { x0 += x1; x1 = __funnelshift_l(x1, x1, (r)); x1 ^= x0; }
    TFR(13) TFR(15) TFR(26) TFR(6)
    x0 += k1; x1 += k2 + 1u;
    TFR(17) TFR(29) TFR(16) TFR(24)
    x0 += k2; x1 += k0 + 2u;
    TFR(13) TFR(15) TFR(26) TFR(6)
    x0 += k0; x1 += k1 + 3u;
    TFR(17) TFR(29) TFR(16) TFR(24)
    x0 += k1; x1 += k2 + 4u;
    TFR(13) TFR(15) TFR(26) TFR(6)
    x0 += k2; x1 += k0 + 5u;
#undef TFR
    return x0 ^ x1;
}

// exact v for the categorical: v = (-logf(u)) * invw, identical arithmetic
// to the validated round-1 kernel (bitwise-stable selection).
__device__ __forceinline__ float exact_v(uint32_t b, float invw)
{
    uint32_t tbits = __umulhi(b, 0x00800000u) + 0x3f800000u; // 1 + (b>>9)*2^-23
    float f = __uint_as_float(tbits) - 1.0f;
    float u = fmaxf(f, 1.17549435e-38f);
    float e = -logf(u);
    return e * invw;
}

// ---------------- kernel A: state transition + process noise -------------
__global__ void k_state(const float* __restrict__ sv,
                        const float* __restrict__ T,
                        const float* __restrict__ Q,
                        uint32_t kn0, uint32_t kn1)
{
    int p = blockIdx.x * blockDim.x + threadIdx.x;
    if (p < 3) g_sum[p] = 0.0f;   // reset accumulators each launch (graph replay)
    if (p == 3) g_done = 0;
    if (p >= NP) return;

    float l00 = sqrtf(Q[0]);
    float l10 = Q[3] / l00, l20 = Q[6] / l00;
    float l11 = sqrtf(Q[4] - l10 * l10);
    float l21 = (Q[7] - l20 * l10) / l11;
    float l22 = sqrtf(Q[8] - l20 * l20 - l21 * l21);

    float z[3];
#pragma unroll
    for (int d = 0; d < 3; ++d) {
        uint32_t b = tf32(kn0, kn1, (uint32_t)(3 * p + d));
        float f = __uint_as_float(0x3f800000u | (b >> 9)) - 1.0f;
        float val = __fadd_rn(__fmul_rn(f, 2.0f), -0.99999994f);
        val = fmaxf(-0.99999994f, val);
        z[d] = 1.41421356237f * erfinvf(val);
    }

    float s0 = sv[3 * p], s1 = sv[3 * p + 1], s2 = sv[3 * p + 2];
    float u0 = T[0] * s0 + T[1] * s1 + T[2] * s2;
    float u1 = T[3] * s0 + T[4] * s1 + T[5] * s2;
    float u2 = T[6] * s0 + T[7] * s1 + T[8] * s2;

    g_state[3 * p + 0] = u0 + z[0] * l00 + z[1] * l10 + z[2] * l20;
    g_state[3 * p + 1] = u1 + z[1] * l11 + z[2] * l21;
    g_state[3 * p + 2] = u2 + z[2] * l22;
}

// ---------------- kernel B: w[a] = sum_b (x[a,b] - F[b].s_a)^2 ------------
// 2 rows per warp: F's strided loads (the wavefront hog) amortized over
// two contiguous x rows. No smem (measured slower in round 2).
__global__ void k_weights(const float* __restrict__ x, const float* __restrict__ F)
{
    int warp = threadIdx.x >> 5, lane = threadIdx.x & 31;
    int a0 = blockIdx.x * 16 + warp * 2;
    int a1 = a0 + 1;

    float s00 = g_state[3 * a0], s01 = g_state[3 * a0 + 1], s02 = g_state[3 * a0 + 2];
    float s10 = g_state[3 * a1], s11 = g_state[3 * a1 + 1], s12 = g_state[3 * a1 + 2];

    const float4* x0 = reinterpret_cast<const float4*>(x + (size_t)a0 * NP);
    const float4* x1 = reinterpret_cast<const float4*>(x + (size_t)a1 * NP);
    const float4* Fv = reinterpret_cast<const float4*>(F);

    float acc0 = 0.0f, acc1 = 0.0f;
#pragma unroll 4
    for (int it = 0; it < NP / 128; ++it) {
        int b4 = it * 32 + lane;
        float4 xa = __ldg(x0 + b4);
        float4 xb = __ldg(x1 + b4);
        float4 f0 = __ldg(Fv + 3 * b4 + 0);
        float4 f1 = __ldg(Fv + 3 * b4 + 1);
        float4 f2 = __ldg(Fv + 3 * b4 + 2);
        float p0 = f0.x * s00 + f0.y * s01 + f0.z * s02;
        float p1 = f0.w * s00 + f1.x * s01 + f1.y * s02;
        float p2 = f1.z * s00 + f1.w * s01 + f2.x * s02;
        float p3 = f2.y * s00 + f2.z * s01 + f2.w * s02;
        float q0 = f0.x * s10 + f0.y * s11 + f0.z * s12;
        float q1 = f0.w * s10 + f1.x * s11 + f1.y * s12;
        float q2 = f1.z * s10 + f1.w * s11 + f2.x * s12;
        float q3 = f2.y * s10 + f2.z * s11 + f2.w * s12;
        float d;
        d = xa.x - p0; acc0 = fmaf(d, d, acc0);
        d = xa.y - p1; acc0 = fmaf(d, d, acc0);
        d = xa.z - p2; acc0 = fmaf(d, d, acc0);
        d = xa.w - p3; acc0 = fmaf(d, d, acc0);
        d = xb.x - q0; acc1 = fmaf(d, d, acc1);
        d = xb.y - q1; acc1 = fmaf(d, d, acc1);
        d = xb.z - q2; acc1 = fmaf(d, d, acc1);
        d = xb.w - q3; acc1 = fmaf(d, d, acc1);
    }
#pragma unroll
    for (int o = 16; o; o >>= 1) {
        acc0 += __shfl_down_sync(0xffffffffu, acc0, o);
        acc1 += __shfl_down_sync(0xffffffffu, acc1, o);
    }
    if (lane == 0) {
        g_invw[a0] = 1.0f / acc0;
        g_invw[a1] = 1.0f / acc1;
    }
}

// ---------------- kernel C: categorical + fused mean-of-gathered ----------
// argmin_j v_j, v_j = (-log u_j)*invw_j.
// Static-threshold screen: thr = exact block-min over iteration k=0.
//   Exact bound: -log(u) >= 1-u = s  (s computed exactly as 2-t).
//   Skip j iff fl(s*invw) > thr*(1+4e-6): provably v_j > thr >= row min,
//   covering 2-ulp logf + 1-ulp mul rounding both ways -> zero flips.
__global__ void k_cat(uint32_t kc0, uint32_t kc1, float* __restrict__ out)
{
    const int row = blockIdx.x;
    const int t = threadIdx.x;
    const float INF = __int_as_float(0x7f800000);
    int lane = t & 31, warp = t >> 5;

    __shared__ float shv[8];
    __shared__ int   shi[8];
    __shared__ float sthr;

    // ---- prologue: iteration k=0, exact, also seeds the threshold ----
    uint32_t nb = (uint32_t)row * (uint32_t)NP + (uint32_t)t;
    float invw0 = __ldg(&g_invw[t]);
    float mv = exact_v(tf32(kc0, kc1, nb), invw0);
    int   mi = t;

    {
        float tv = mv;
#pragma unroll
        for (int o = 16; o; o >>= 1)
            tv = fminf(tv, __shfl_xor_sync(0xffffffffu, tv, o));
        if (lane == 0) shv[warp] = tv;
        __syncthreads();
        if (t == 0) {
            float m = shv[0];
#pragma unroll
            for (int wq = 1; wq < 8; ++wq) m = fminf(m, shv[wq]);
            sthr = m * 1.000004f;   // fudged static threshold
        }
        __syncthreads();
    }
    const float thr2 = sthr;
    __syncthreads();   // shv reused below; make sure everyone read sthr

    // ---- main loop: k = 1..31 with screen ----
    int j = t;
    uint32_t nbk = nb;
#pragma unroll 4
    for (int k = 1; k < NP / 256; ++k) {
        j += 256;
        nbk += 256u;
        uint32_t b = tf32(kc0, kc1, nbk);
        uint32_t tbits = __umulhi(b, 0x00800000u) + 0x3f800000u;
        float s = 2.0f - __uint_as_float(tbits);        // = 1-u, exact
        float invw = __ldg(&g_invw[j]);
        bool maybe = (s * invw) <= thr2;                // survive screen?
        if (__ballot_sync(0xffffffffu, maybe)) {
            float f = __uint_as_float(tbits) - 1.0f;
            float u = fmaxf(f, 1.17549435e-38f);
            float v = (-logf(u)) * invw;
            if (v < mv) { mv = v; mi = j; }             // strict <: first wins
        }
    }

    // ---- block argmin reduce (value, then lower index on exact ties) ----
#pragma unroll
    for (int o = 16; o; o >>= 1) {
        float ov = __shfl_down_sync(0xffffffffu, mv, o);
        int   oi = __shfl_down_sync(0xffffffffu, mi, o);
        if (ov < mv || (ov == mv && oi < mi)) { mv = ov; mi = oi; }
    }
    if (lane == 0) { shv[warp] = mv; shi[warp] = mi; }
    __syncthreads();
    if (warp == 0) {
        float v2 = (lane < 8) ? shv[lane] : INF;
        int   i2 = (lane < 8) ? shi[lane] : 0x7fffffff;
#pragma unroll
        for (int o = 4; o; o >>= 1) {
            float ov = __shfl_down_sync(0xffffffffu, v2, o);
            int   oi = __shfl_down_sync(0xffffffffu, i2, o);
            if (ov < v2 || (ov == v2 && oi < i2)) { v2 = ov; i2 = oi; }
        }
        if (lane == 0) {
            atomicAdd(&g_sum[0], g_state[3 * i2 + 0]);
            atomicAdd(&g_sum[1], g_state[3 * i2 + 1]);
            atomicAdd(&g_sum[2], g_state[3 * i2 + 2]);
            __threadfence();
            if (atomicAdd(&g_done, 1) == (int)gridDim.x - 1) {
                out[0] = g_sum[0] * (1.0f / NP);
                out[1] = g_sum[1] * (1.0f / NP);
                out[2] = g_sum[2] * (1.0f / NP);
            }
        }
    }
}

// ---------------- host: key derivation (fold-like split) ------------------
static void h_tf(uint32_t k0, uint32_t k1, uint32_t x0, uint32_t x1,
                 uint32_t& y0, uint32_t& y1)
{
    uint32_t k2 = k0 ^ k1 ^ 0x1BD11BDAu;
    x0 += k0; x1 += k1;
    const int R0[4] = {13, 15, 26, 6}, R1[4] = {17, 29, 16, 24};
    const int* RS[5] = {R0, R1, R0, R1, R0};
    const uint32_t ks[3] = {k0, k1, k2};
    for (int g = 0; g < 5; ++g) {
        for (int q = 0; q < 4; ++q) {
            x0 += x1;
            int r = RS[g][q];
            x1 = (x1 << r) | (x1 >> (32 - r));
            x1 ^= x0;
        }
        x0 += ks[(g + 1) % 3];
        x1 += ks[(g + 2) % 3] + (uint32_t)(g + 1);
    }
    y0 = x0; y1 = x1;
}

extern "C" void kernel_launch(void* const* d_in, const int* in_sizes, int n_in,
                              void* d_out, int out_size)
{
    const float* x  = (const float*)d_in[0];  // inputs (1, C, P)
    const float* sv = (const float*)d_in[1];  // state_vector (P, 3)
    const float* T  = (const float*)d_in[2];  // transition (3, 3)
    const float* Q  = (const float*)d_in[3];  // process noise cov (3, 3)
    const float* F  = (const float*)d_in[4];  // forward_matrix (C, 3)

    uint32_t kn0, kn1, kc0, kc1;
    h_tf(0u, 42u, 0u, 0u, kn0, kn1);  // k_noise
    h_tf(0u, 42u, 0u, 1u, kc0, kc1);  // k_cat

    k_state  <<<NP / 256, 256>>>(sv, T, Q, kn0, kn1);
    k_weights<<<NP / 16,  256>>>(x, F);
    k_cat    <<<NP,       256>>>(kc0, kc1, (float*)d_out);
}